// round 1
// baseline (speedup 1.0000x reference)
#include <cuda_runtime.h>
#include <math.h>

// Problem constants (fixed shapes for this dataset)
#define GRES   128                 // plane H=W, line L
#define NPIX   (GRES * GRES)       // 16384
#define SC     96                  // S(6) * C(16) fused channel dim
#define MAXPTS (2048 * 256)        // 524288 points

// Scratch (static device globals — no allocation at runtime)
__device__ float g_planesT[3 * NPIX * SC];   // [p][pixel][sc]   18.9 MB
__device__ float g_linesT [3 * GRES * SC];   // [p][z][sc]
__device__ float g_bwf    [MAXPTS * 6];      // per-point 6-vector field

// ---------------------------------------------------------------------------
// Transpose planes (3,96,128,128) -> (3, 16384, 96), pixel-major channels.
// Tiled through shared memory: coalesced loads (pixel-contig) and coalesced
// stores (channel-contig), pad row stride to 65 to kill bank conflicts.
// ---------------------------------------------------------------------------
__global__ void transpose_planes_kernel(const float* __restrict__ planes) {
    __shared__ float tile[SC][65];
    const int p      = blockIdx.y;
    const int pxBase = blockIdx.x * 64;
    const int tid    = threadIdx.x;             // 256 threads

    const float* in = planes + (size_t)p * SC * NPIX;
    #pragma unroll
    for (int i = tid; i < SC * 64; i += 256) {
        int sc = i >> 6;            // 0..95
        int px = i & 63;            // 0..63
        tile[sc][px] = in[(size_t)sc * NPIX + pxBase + px];
    }
    __syncthreads();

    float* out = g_planesT + (size_t)p * NPIX * SC;
    #pragma unroll
    for (int i = tid; i < SC * 64; i += 256) {
        int px = i / SC;            // 0..63
        int sc = i - px * SC;       // 0..95
        out[(size_t)(pxBase + px) * SC + sc] = tile[sc][px];
    }
}

// Transpose lines (3,96,128) -> (3,128,96). Tiny (36864 elems).
__global__ void transpose_lines_kernel(const float* __restrict__ lines) {
    int o = blockIdx.x * 256 + threadIdx.x;
    if (o >= 3 * GRES * SC) return;
    int sc = o % SC;
    int t  = o / SC;
    int z  = t % GRES;
    int p  = t / GRES;
    g_linesT[o] = lines[((size_t)p * SC + sc) * GRES + z];
}

// ---------------------------------------------------------------------------
// Sample kernel: block = (96, PTS_PER_BLK). Each warp = 32 consecutive
// channels of ONE point -> every gather is one coalesced 128B line.
// Lane channel c: s = c>>4. 16-lane xor-shfl reduction -> g_bwf[pt*6+s].
// ---------------------------------------------------------------------------
#define PTS_PER_BLK 4

__global__ __launch_bounds__(96 * PTS_PER_BLK)
void sample_kernel(const float* __restrict__ xyz,
                   const float* __restrict__ aabb,
                   int npts) {
    const int c  = threadIdx.x;                              // 0..95
    const int pt = blockIdx.x * PTS_PER_BLK + threadIdx.y;
    if (pt >= npts) return;   // whole warps exit together (96 = 3 warps/pt)

    // Point coords (broadcast loads: all lanes same address)
    const float P0 = __ldg(&xyz[pt * 3 + 0]);
    const float P1 = __ldg(&xyz[pt * 3 + 1]);
    const float P2 = __ldg(&xyz[pt * 3 + 2]);

    const float lo0 = __ldg(&aabb[0]), lo1 = __ldg(&aabb[1]), lo2 = __ldg(&aabb[2]);
    const float hi0 = __ldg(&aabb[3]), hi1 = __ldg(&aabb[4]), hi2 = __ldg(&aabb[5]);

    float xn[3];
    xn[0] = (P0 - lo0) * (2.0f / (hi0 - lo0)) - 1.0f;
    xn[1] = (P1 - lo1) * (2.0f / (hi1 - lo1)) - 1.0f;
    xn[2] = (P2 - lo2) * (2.0f / (hi2 - lo2)) - 1.0f;

    // Per-axis grid coordinates, computed once and shared by all 3 planes.
    int   col0[3], col1[3], row0[3], row1[3];
    float wgt[3];
    #pragma unroll
    for (int d = 0; d < 3; d++) {
        float f = fmaf(xn[d], 63.5f, 63.5f);          // (xn+1)*0.5*(G-1)
        f = fminf(fmaxf(f, 0.0f), 127.0f);
        float ff = floorf(f);
        int   i0 = (int)ff;
        int   i1 = min(i0 + 1, GRES - 1);
        wgt[d]  = f - ff;
        col0[d] = i0 * SC + c;        // x-offset (or line z-offset) incl. channel
        col1[d] = i1 * SC + c;
        row0[d] = i0 * (GRES * SC);   // y-row offset
        row1[d] = i1 * (GRES * SC);
    }

    const int M0s[3] = {0, 0, 1};     // MAT_MODE first coord -> W axis
    const int M1s[3] = {1, 2, 2};     // MAT_MODE second coord -> H axis
    const int MZs[3] = {2, 1, 0};     // VEC_MODE -> line axis

    float acc = 0.0f;
    #pragma unroll
    for (int p = 0; p < 3; p++) {
        const int m0 = M0s[p], m1 = M1s[p], mz = MZs[p];
        const float* __restrict__ PB = g_planesT + (size_t)p * NPIX * SC;
        const float* __restrict__ LB = g_linesT  + (size_t)p * GRES * SC;

        const float f00 = __ldg(PB + row0[m1] + col0[m0]);
        const float f01 = __ldg(PB + row0[m1] + col1[m0]);
        const float f10 = __ldg(PB + row1[m1] + col0[m0]);
        const float f11 = __ldg(PB + row1[m1] + col1[m0]);
        const float l0  = __ldg(LB + col0[mz]);
        const float l1  = __ldg(LB + col1[mz]);

        const float wx = wgt[m0], wy = wgt[m1], wz = wgt[mz];
        const float top = fmaf(wx, f01 - f00, f00);
        const float bot = fmaf(wx, f11 - f10, f10);
        const float pv  = fmaf(wy, bot - top, top);
        const float lv  = fmaf(wz, l1 - l0, l0);
        acc = fmaf(pv, lv, acc);
    }

    // Reduce over the 16 channels belonging to one s (lanes [0,16) / [16,32))
    #pragma unroll
    for (int m = 8; m; m >>= 1)
        acc += __shfl_xor_sync(0xffffffffu, acc, m);

    if ((c & 15) == 0)
        g_bwf[(size_t)pt * 6 + (c >> 4)] = acc;
}

// ---------------------------------------------------------------------------
// Rodrigues / SE(3) exponential warp, one thread per point.
// Uses K^2 = w w^T - (w.w) I so no 3x3 matrices are materialized.
// Handles the theta = sqrt(clip(|w|^2,1e-6)) case where w-hat is not unit.
// ---------------------------------------------------------------------------
__global__ void warp_kernel(const float* __restrict__ xyz,
                            const float* __restrict__ vd,
                            float* __restrict__ out,
                            int npts) {
    int pt = blockIdx.x * 256 + threadIdx.x;
    if (pt >= npts) return;

    const float* b = g_bwf + (size_t)pt * 6;
    float w0 = b[0], w1 = b[1], w2 = b[2];
    float v0 = b[3], v1 = b[4], v2 = b[5];

    float th2 = fmaf(w0, w0, fmaf(w1, w1, w2 * w2));
    th2 = fmaxf(th2, 1e-6f);
    float th  = sqrtf(th2);
    float inv = 1.0f / th;
    w0 *= inv; w1 *= inv; w2 *= inv;
    v0 *= inv; v1 *= inv; v2 *= inv;

    float q  = fmaf(w0, w0, fmaf(w1, w1, w2 * w2));   // w-hat . w-hat (<=1)
    float s  = sinf(th);
    float co = cosf(th);
    float cm = 1.0f - co;
    float ts = th - s;

    float rD = 1.0f - cm * q;    // R = rD*I + s*K + cm*wwT
    float pD = th - ts * q;      // P = pD*I + cm*K + ts*wwT

    float X0 = xyz[pt * 3 + 0], X1 = xyz[pt * 3 + 1], X2 = xyz[pt * 3 + 2];
    float D0 = vd [pt * 3 + 0], D1 = vd [pt * 3 + 1], D2 = vd [pt * 3 + 2];

    // t = P v
    float wdV = fmaf(w0, v0, fmaf(w1, v1, w2 * v2));
    float t0 = pD * v0 + cm * (w1 * v2 - w2 * v1) + ts * w0 * wdV;
    float t1 = pD * v1 + cm * (w2 * v0 - w0 * v2) + ts * w1 * wdV;
    float t2 = pD * v2 + cm * (w0 * v1 - w1 * v0) + ts * w2 * wdV;

    // xw = R x + t
    float wdX = fmaf(w0, X0, fmaf(w1, X1, w2 * X2));
    float xw0 = rD * X0 + s * (w1 * X2 - w2 * X1) + cm * w0 * wdX + t0;
    float xw1 = rD * X1 + s * (w2 * X0 - w0 * X2) + cm * w1 * wdX + t1;
    float xw2 = rD * X2 + s * (w0 * X1 - w1 * X0) + cm * w2 * wdX + t2;

    // vw = R d
    float wdD = fmaf(w0, D0, fmaf(w1, D1, w2 * D2));
    float vw0 = rD * D0 + s * (w1 * D2 - w2 * D1) + cm * w0 * wdD;
    float vw1 = rD * D1 + s * (w2 * D0 - w0 * D2) + cm * w1 * wdD;
    float vw2 = rD * D2 + s * (w0 * D1 - w1 * D0) + cm * w2 * wdD;

    out[(size_t)pt * 3 + 0] = xw0;
    out[(size_t)pt * 3 + 1] = xw1;
    out[(size_t)pt * 3 + 2] = xw2;
    size_t off = (size_t)npts * 3;
    out[off + (size_t)pt * 3 + 0] = vw0;
    out[off + (size_t)pt * 3 + 1] = vw1;
    out[off + (size_t)pt * 3 + 2] = vw2;
}

// ---------------------------------------------------------------------------
// Launch: transpose -> sample -> warp. Graph-capturable, allocation-free.
// Inputs (metadata order): xyz, viewdirs, transforms(unused),
//                          ray_valid(unused), planes, lines, ray_aabb
// ---------------------------------------------------------------------------
extern "C" void kernel_launch(void* const* d_in, const int* in_sizes, int n_in,
                              void* d_out, int out_size) {
    const float* xyz    = (const float*)d_in[0];
    const float* vdirs  = (const float*)d_in[1];
    const float* planes = (const float*)d_in[4];
    const float* lines  = (const float*)d_in[5];
    const float* aabb   = (const float*)d_in[6];
    float* out = (float*)d_out;

    const int npts = in_sizes[0] / 3;

    transpose_planes_kernel<<<dim3(NPIX / 64, 3), 256>>>(planes);
    transpose_lines_kernel<<<(3 * GRES * SC + 255) / 256, 256>>>(lines);

    dim3 sblk(96, PTS_PER_BLK);
    sample_kernel<<<(npts + PTS_PER_BLK - 1) / PTS_PER_BLK, sblk>>>(xyz, aabb, npts);

    warp_kernel<<<(npts + 255) / 256, 256>>>(xyz, vdirs, out, npts);
}

// round 2
// speedup vs baseline: 1.9754x; 1.9754x over previous
#include <cuda_runtime.h>
#include <cuda_fp16.h>
#include <math.h>

// Fixed shapes for this dataset
#define GRES   128                 // plane H=W, line L
#define NPIX   (GRES * GRES)       // 16384
#define SC     96                  // S(6) * C(16) fused channel dim
#define VPP    24                  // uint2 (4 halves) per pixel: 24*4 = 96 ch

// Scratch: fp16 tables, pixel-major channels (no runtime allocation)
__device__ uint2 g_planesH[3 * NPIX * VPP];   // 9.4 MB
__device__ uint2 g_linesH [3 * GRES * VPP];   // 73 KB (L1-resident)

// ---------------------------------------------------------------------------
// Transpose + fp32->fp16 convert planes (3,96,128,128) -> (3,16384,96 halves)
// ---------------------------------------------------------------------------
__global__ void prep_planes(const float* __restrict__ planes) {
    __shared__ float tile[SC][65];
    const int p      = blockIdx.y;
    const int pxBase = blockIdx.x * 64;
    const int tid    = threadIdx.x;            // 256 threads

    const float* in = planes + (size_t)p * SC * NPIX;
    #pragma unroll
    for (int i = tid; i < SC * 64; i += 256) {
        int sc = i >> 6;
        int px = i & 63;
        tile[sc][px] = in[(size_t)sc * NPIX + pxBase + px];
    }
    __syncthreads();

    unsigned* out = reinterpret_cast<unsigned*>(g_planesH)
                  + ((size_t)p * NPIX + pxBase) * 48;      // 48 half2 per pixel
    #pragma unroll
    for (int i = tid; i < 64 * 48; i += 256) {
        int px = i / 48;
        int u  = i - px * 48;                  // half2 index: channels 2u, 2u+1
        __half2 h = __floats2half2_rn(tile[2 * u][px], tile[2 * u + 1][px]);
        out[(size_t)px * 48 + u] = *reinterpret_cast<unsigned*>(&h);
    }
}

// Transpose + convert lines (3,96,128) -> (3,128,96 halves)
__global__ void prep_lines(const float* __restrict__ lines) {
    int o = blockIdx.x * 256 + threadIdx.x;    // over 3*128*48 half2 slots
    if (o >= 3 * GRES * 48) return;
    int u = o % 48;
    int t = o / 48;
    int z = t % GRES;
    int p = t / GRES;
    const float* base = lines + (size_t)p * SC * GRES + z;
    float a = base[(size_t)(2 * u)     * GRES];
    float b = base[(size_t)(2 * u + 1) * GRES];
    __half2 h = __floats2half2_rn(a, b);
    reinterpret_cast<unsigned*>(g_linesH)[o] = *reinterpret_cast<unsigned*>(&h);
}

// ---------------------------------------------------------------------------
// Fused sample + Rodrigues warp.
// Block = 192 threads = 8 points x 24 lanes. Lane l owns channels [4l, 4l+4):
// one uint2 (4 halves) per gather -> 192 contiguous bytes per point-gather,
// perfectly sector-aligned (192 = 6 x 32B). s-group = 4 lanes (16 channels),
// reduced with two xor-shuffles. Rodrigues runs on threads 0..7 after smem
// exchange — no global bwf round trip.
// ---------------------------------------------------------------------------
__device__ __forceinline__ void ld4(const uint2* __restrict__ p, size_t idx,
                                    float f[4]) {
    uint2 q = __ldg(p + idx);
    __half2 h0 = *reinterpret_cast<__half2*>(&q.x);
    __half2 h1 = *reinterpret_cast<__half2*>(&q.y);
    float2 a = __half22float2(h0);
    float2 b = __half22float2(h1);
    f[0] = a.x; f[1] = a.y; f[2] = b.x; f[3] = b.y;
}

__global__ __launch_bounds__(192)
void fused_kernel(const float* __restrict__ xyz,
                  const float* __restrict__ vd,
                  const float* __restrict__ aabb,
                  float* __restrict__ out,
                  int npts) {
    __shared__ float s_bwf[8][6];

    const int tid  = threadIdx.x;
    const int pidx = tid / 24;                 // 0..7
    const int l    = tid - pidx * 24;          // 0..23
    const int pt   = blockIdx.x * 8 + pidx;
    const bool active = (pt < npts);

    float acc = 0.0f;
    if (active) {
        const float P0 = __ldg(&xyz[pt * 3 + 0]);
        const float P1 = __ldg(&xyz[pt * 3 + 1]);
        const float P2 = __ldg(&xyz[pt * 3 + 2]);

        const float lo0 = __ldg(&aabb[0]), lo1 = __ldg(&aabb[1]), lo2 = __ldg(&aabb[2]);
        const float hi0 = __ldg(&aabb[3]), hi1 = __ldg(&aabb[4]), hi2 = __ldg(&aabb[5]);

        float xn[3];
        xn[0] = (P0 - lo0) * (2.0f / (hi0 - lo0)) - 1.0f;
        xn[1] = (P1 - lo1) * (2.0f / (hi1 - lo1)) - 1.0f;
        xn[2] = (P2 - lo2) * (2.0f / (hi2 - lo2)) - 1.0f;

        int i0[3], i1[3];
        float w[3];
        #pragma unroll
        for (int d = 0; d < 3; d++) {
            float f = fmaf(xn[d], 63.5f, 63.5f);       // (xn+1)*0.5*(G-1)
            f = fminf(fmaxf(f, 0.0f), 127.0f);
            float ff = floorf(f);
            i0[d] = (int)ff;
            i1[d] = min(i0[d] + 1, GRES - 1);
            w[d]  = f - ff;
        }

        const int M0s[3] = {0, 0, 1};
        const int M1s[3] = {1, 2, 2};
        const int MZs[3] = {2, 1, 0};

        #pragma unroll
        for (int p = 0; p < 3; p++) {
            const int m0 = M0s[p], m1 = M1s[p], mz = MZs[p];
            const uint2* __restrict__ PB = g_planesH + (size_t)p * NPIX * VPP;
            const uint2* __restrict__ LB = g_linesH  + (size_t)p * GRES * VPP;

            const int r0 = i0[m1] * GRES;
            const int r1 = i1[m1] * GRES;

            float f00[4], f01[4], f10[4], f11[4], l0v[4], l1v[4];
            ld4(PB, (size_t)(r0 + i0[m0]) * VPP + l, f00);
            ld4(PB, (size_t)(r0 + i1[m0]) * VPP + l, f01);
            ld4(PB, (size_t)(r1 + i0[m0]) * VPP + l, f10);
            ld4(PB, (size_t)(r1 + i1[m0]) * VPP + l, f11);
            ld4(LB, (size_t)i0[mz] * VPP + l, l0v);
            ld4(LB, (size_t)i1[mz] * VPP + l, l1v);

            const float wx = w[m0], wy = w[m1], wz = w[mz];
            #pragma unroll
            for (int j = 0; j < 4; j++) {
                float top = fmaf(wx, f01[j] - f00[j], f00[j]);
                float bot = fmaf(wx, f11[j] - f10[j], f10[j]);
                float pv  = fmaf(wy, bot - top, top);
                float lv  = fmaf(wz, l1v[j] - l0v[j], l0v[j]);
                acc = fmaf(pv, lv, acc);
            }
        }
    }

    // Reduce 4 lanes (16 channels) per s-group. Groups are lane-aligned mod 4.
    acc += __shfl_xor_sync(0xffffffffu, acc, 1);
    acc += __shfl_xor_sync(0xffffffffu, acc, 2);
    if (active && (l & 3) == 0)
        s_bwf[pidx][l >> 2] = acc;

    __syncthreads();

    // Rodrigues / SE(3) exp map: one thread per point
    if (tid < 8) {
        const int pw = blockIdx.x * 8 + tid;
        if (pw < npts) {
            float w0 = s_bwf[tid][0], w1 = s_bwf[tid][1], w2 = s_bwf[tid][2];
            float v0 = s_bwf[tid][3], v1 = s_bwf[tid][4], v2 = s_bwf[tid][5];

            float th2 = fmaf(w0, w0, fmaf(w1, w1, w2 * w2));
            th2 = fmaxf(th2, 1e-6f);
            float th  = sqrtf(th2);
            float inv = 1.0f / th;
            w0 *= inv; w1 *= inv; w2 *= inv;
            v0 *= inv; v1 *= inv; v2 *= inv;

            float q  = fmaf(w0, w0, fmaf(w1, w1, w2 * w2));
            float s  = sinf(th);
            float co = cosf(th);
            float cm = 1.0f - co;
            float ts = th - s;

            float rD = 1.0f - cm * q;
            float pD = th - ts * q;

            float X0 = xyz[pw * 3 + 0], X1 = xyz[pw * 3 + 1], X2 = xyz[pw * 3 + 2];
            float D0 = vd [pw * 3 + 0], D1 = vd [pw * 3 + 1], D2 = vd [pw * 3 + 2];

            float wdV = fmaf(w0, v0, fmaf(w1, v1, w2 * v2));
            float t0 = pD * v0 + cm * (w1 * v2 - w2 * v1) + ts * w0 * wdV;
            float t1 = pD * v1 + cm * (w2 * v0 - w0 * v2) + ts * w1 * wdV;
            float t2 = pD * v2 + cm * (w0 * v1 - w1 * v0) + ts * w2 * wdV;

            float wdX = fmaf(w0, X0, fmaf(w1, X1, w2 * X2));
            float xw0 = rD * X0 + s * (w1 * X2 - w2 * X1) + cm * w0 * wdX + t0;
            float xw1 = rD * X1 + s * (w2 * X0 - w0 * X2) + cm * w1 * wdX + t1;
            float xw2 = rD * X2 + s * (w0 * X1 - w1 * X0) + cm * w2 * wdX + t2;

            float wdD = fmaf(w0, D0, fmaf(w1, D1, w2 * D2));
            float vw0 = rD * D0 + s * (w1 * D2 - w2 * D1) + cm * w0 * wdD;
            float vw1 = rD * D1 + s * (w2 * D0 - w0 * D2) + cm * w1 * wdD;
            float vw2 = rD * D2 + s * (w0 * D1 - w1 * D0) + cm * w2 * wdD;

            out[(size_t)pw * 3 + 0] = xw0;
            out[(size_t)pw * 3 + 1] = xw1;
            out[(size_t)pw * 3 + 2] = xw2;
            size_t off = (size_t)npts * 3;
            out[off + (size_t)pw * 3 + 0] = vw0;
            out[off + (size_t)pw * 3 + 1] = vw1;
            out[off + (size_t)pw * 3 + 2] = vw2;
        }
    }
}

// ---------------------------------------------------------------------------
// Launch: prep (transpose+fp16) -> fused sample+warp. Graph-capturable.
// Inputs: xyz, viewdirs, transforms(unused), ray_valid(unused),
//         planes, lines, ray_aabb
// ---------------------------------------------------------------------------
extern "C" void kernel_launch(void* const* d_in, const int* in_sizes, int n_in,
                              void* d_out, int out_size) {
    const float* xyz    = (const float*)d_in[0];
    const float* vdirs  = (const float*)d_in[1];
    const float* planes = (const float*)d_in[4];
    const float* lines  = (const float*)d_in[5];
    const float* aabb   = (const float*)d_in[6];
    float* out = (float*)d_out;

    const int npts = in_sizes[0] / 3;

    prep_planes<<<dim3(NPIX / 64, 3), 256>>>(planes);
    prep_lines<<<(3 * GRES * 48 + 255) / 256, 256>>>(lines);

    fused_kernel<<<(npts + 7) / 8, 192>>>(xyz, vdirs, aabb, out, npts);
}

// round 3
// speedup vs baseline: 2.1695x; 1.0983x over previous
#include <cuda_runtime.h>
#include <cuda_fp16.h>
#include <math.h>

// Fixed shapes
#define GRES   128
#define NPIX   (GRES * GRES)       // 16384
#define SC     96                  // S(6)*C(16)
#define LPP    24                  // lanes per point (4 channels/lane)

// Corner-paired fp16 tables (no runtime allocation).
// Plane record [p][y][x][l] = uint4{ 4ch of (y,x), 4ch of (y,min(x+1,127)) }
// Line  record [p][z][l]    = uint4{ 4ch of z,     4ch of min(z+1,127)     }
__device__ uint4 g_planesP[3 * NPIX * LPP];   // 18.9 MB
__device__ uint4 g_linesP [3 * GRES * LPP];   // 147 KB (L1-resident)

// ---------------------------------------------------------------------------
// Build paired plane table. Block handles one (plane, y, 64-wide x chunk).
// Tile has +1 x-halo so the (x, x+1) pair never leaves the block.
// ---------------------------------------------------------------------------
__global__ void prep_planes(const float* __restrict__ planes) {
    __shared__ float tile[SC][65];             // [channel][x within chunk(+halo)]
    const int p   = blockIdx.y;
    const int y   = blockIdx.x >> 1;
    const int xb  = (blockIdx.x & 1) * 64;
    const int tid = threadIdx.x;               // 256 threads

    const float* in = planes + ((size_t)p * SC) * NPIX + y * GRES;
    for (int i = tid; i < SC * 65; i += 256) {
        int sc = i / 65;
        int j  = i - sc * 65;
        tile[sc][j] = in[(size_t)sc * NPIX + min(xb + j, GRES - 1)];
    }
    __syncthreads();

    uint4* out = g_planesP + (((size_t)p * GRES + y) * GRES + xb) * LPP;
    for (int i = tid; i < 64 * LPP; i += 256) {
        int x = i / LPP;
        int l = i - x * LPP;
        __half2 a0 = __floats2half2_rn(tile[4 * l + 0][x],     tile[4 * l + 1][x]);
        __half2 a1 = __floats2half2_rn(tile[4 * l + 2][x],     tile[4 * l + 3][x]);
        __half2 b0 = __floats2half2_rn(tile[4 * l + 0][x + 1], tile[4 * l + 1][x + 1]);
        __half2 b1 = __floats2half2_rn(tile[4 * l + 2][x + 1], tile[4 * l + 3][x + 1]);
        uint4 q;
        q.x = *reinterpret_cast<unsigned*>(&a0);
        q.y = *reinterpret_cast<unsigned*>(&a1);
        q.z = *reinterpret_cast<unsigned*>(&b0);
        q.w = *reinterpret_cast<unsigned*>(&b1);
        out[(size_t)x * LPP + l] = q;
    }
}

// Build paired line table: one thread per output record (tiny).
__global__ void prep_lines(const float* __restrict__ lines) {
    int o = blockIdx.x * 256 + threadIdx.x;    // over 3*128*24 records
    if (o >= 3 * GRES * LPP) return;
    int l = o % LPP;
    int t = o / LPP;
    int z = t % GRES;
    int p = t / GRES;
    int z1 = min(z + 1, GRES - 1);
    const float* base = lines + (size_t)p * SC * GRES;
    __half2 a0 = __floats2half2_rn(base[(size_t)(4*l+0)*GRES + z],  base[(size_t)(4*l+1)*GRES + z]);
    __half2 a1 = __floats2half2_rn(base[(size_t)(4*l+2)*GRES + z],  base[(size_t)(4*l+3)*GRES + z]);
    __half2 b0 = __floats2half2_rn(base[(size_t)(4*l+0)*GRES + z1], base[(size_t)(4*l+1)*GRES + z1]);
    __half2 b1 = __floats2half2_rn(base[(size_t)(4*l+2)*GRES + z1], base[(size_t)(4*l+3)*GRES + z1]);
    uint4 q;
    q.x = *reinterpret_cast<unsigned*>(&a0);
    q.y = *reinterpret_cast<unsigned*>(&a1);
    q.z = *reinterpret_cast<unsigned*>(&b0);
    q.w = *reinterpret_cast<unsigned*>(&b1);
    g_linesP[o] = q;
}

// ---------------------------------------------------------------------------
// Fused sample + Rodrigues. Block = 192 threads = 8 pts x 24 lanes.
// Per plane: 2 paired LDG.128 (both x-corners each) + 1 paired line LDG.128.
// ---------------------------------------------------------------------------
__device__ __forceinline__ void unp2(unsigned u, float& a, float& b) {
    __half2 h = *reinterpret_cast<__half2*>(&u);
    float2 f = __half22float2(h);
    a = f.x; b = f.y;
}

__global__ __launch_bounds__(192)
void fused_kernel(const float* __restrict__ xyz,
                  const float* __restrict__ vd,
                  const float* __restrict__ aabb,
                  float* __restrict__ out,
                  int npts) {
    __shared__ float s_bwf[8][6];

    const int tid  = threadIdx.x;
    const int pidx = tid / LPP;                // 0..7
    const int l    = tid - pidx * LPP;         // 0..23
    const int pt   = blockIdx.x * 8 + pidx;
    const bool active = (pt < npts);

    float acc = 0.0f;
    if (active) {
        const float P0 = __ldg(&xyz[pt * 3 + 0]);
        const float P1 = __ldg(&xyz[pt * 3 + 1]);
        const float P2 = __ldg(&xyz[pt * 3 + 2]);

        const float lo0 = __ldg(&aabb[0]), lo1 = __ldg(&aabb[1]), lo2 = __ldg(&aabb[2]);
        const float hi0 = __ldg(&aabb[3]), hi1 = __ldg(&aabb[4]), hi2 = __ldg(&aabb[5]);

        float xn[3];
        xn[0] = (P0 - lo0) * (2.0f / (hi0 - lo0)) - 1.0f;
        xn[1] = (P1 - lo1) * (2.0f / (hi1 - lo1)) - 1.0f;
        xn[2] = (P2 - lo2) * (2.0f / (hi2 - lo2)) - 1.0f;

        int i0[3], i1[3];
        float w[3];
        #pragma unroll
        for (int d = 0; d < 3; d++) {
            float f = fmaf(xn[d], 63.5f, 63.5f);
            f = fminf(fmaxf(f, 0.0f), 127.0f);
            float ff = floorf(f);
            i0[d] = (int)ff;
            i1[d] = min(i0[d] + 1, GRES - 1);
            w[d]  = f - ff;
        }

        const int M0s[3] = {0, 0, 1};
        const int M1s[3] = {1, 2, 2};
        const int MZs[3] = {2, 1, 0};

        #pragma unroll
        for (int p = 0; p < 3; p++) {
            const int m0 = M0s[p], m1 = M1s[p], mz = MZs[p];
            const uint4* __restrict__ PB = g_planesP + (size_t)p * NPIX * LPP;
            const uint4* __restrict__ LB = g_linesP  + (size_t)p * GRES * LPP;

            uint4 q0 = __ldg(PB + ((size_t)(i0[m1] * GRES + i0[m0]) * LPP + l)); // f00,f01
            uint4 q1 = __ldg(PB + ((size_t)(i1[m1] * GRES + i0[m0]) * LPP + l)); // f10,f11
            uint4 lq = __ldg(LB + ((size_t)i0[mz] * LPP + l));                   // l0,l1

            float f00[4], f01[4], f10[4], f11[4], l0v[4], l1v[4];
            unp2(q0.x, f00[0], f00[1]); unp2(q0.y, f00[2], f00[3]);
            unp2(q0.z, f01[0], f01[1]); unp2(q0.w, f01[2], f01[3]);
            unp2(q1.x, f10[0], f10[1]); unp2(q1.y, f10[2], f10[3]);
            unp2(q1.z, f11[0], f11[1]); unp2(q1.w, f11[2], f11[3]);
            unp2(lq.x, l0v[0], l0v[1]); unp2(lq.y, l0v[2], l0v[3]);
            unp2(lq.z, l1v[0], l1v[1]); unp2(lq.w, l1v[2], l1v[3]);

            const float wx = w[m0], wy = w[m1], wz = w[mz];
            #pragma unroll
            for (int j = 0; j < 4; j++) {
                float top = fmaf(wx, f01[j] - f00[j], f00[j]);
                float bot = fmaf(wx, f11[j] - f10[j], f10[j]);
                float pv  = fmaf(wy, bot - top, top);
                float lv  = fmaf(wz, l1v[j] - l0v[j], l0v[j]);
                acc = fmaf(pv, lv, acc);
            }
        }
    }

    acc += __shfl_xor_sync(0xffffffffu, acc, 1);
    acc += __shfl_xor_sync(0xffffffffu, acc, 2);
    if (active && (l & 3) == 0)
        s_bwf[pidx][l >> 2] = acc;

    __syncthreads();

    if (tid < 8) {
        const int pw = blockIdx.x * 8 + tid;
        if (pw < npts) {
            float w0 = s_bwf[tid][0], w1 = s_bwf[tid][1], w2 = s_bwf[tid][2];
            float v0 = s_bwf[tid][3], v1 = s_bwf[tid][4], v2 = s_bwf[tid][5];

            float th2 = fmaf(w0, w0, fmaf(w1, w1, w2 * w2));
            th2 = fmaxf(th2, 1e-6f);
            float th  = sqrtf(th2);
            float inv = 1.0f / th;
            w0 *= inv; w1 *= inv; w2 *= inv;
            v0 *= inv; v1 *= inv; v2 *= inv;

            float q  = fmaf(w0, w0, fmaf(w1, w1, w2 * w2));
            float s  = sinf(th);
            float co = cosf(th);
            float cm = 1.0f - co;
            float ts = th - s;

            float rD = 1.0f - cm * q;
            float pD = th - ts * q;

            float X0 = xyz[pw * 3 + 0], X1 = xyz[pw * 3 + 1], X2 = xyz[pw * 3 + 2];
            float D0 = vd [pw * 3 + 0], D1 = vd [pw * 3 + 1], D2 = vd [pw * 3 + 2];

            float wdV = fmaf(w0, v0, fmaf(w1, v1, w2 * v2));
            float t0 = pD * v0 + cm * (w1 * v2 - w2 * v1) + ts * w0 * wdV;
            float t1 = pD * v1 + cm * (w2 * v0 - w0 * v2) + ts * w1 * wdV;
            float t2 = pD * v2 + cm * (w0 * v1 - w1 * v0) + ts * w2 * wdV;

            float wdX = fmaf(w0, X0, fmaf(w1, X1, w2 * X2));
            float xw0 = rD * X0 + s * (w1 * X2 - w2 * X1) + cm * w0 * wdX + t0;
            float xw1 = rD * X1 + s * (w2 * X0 - w0 * X2) + cm * w1 * wdX + t1;
            float xw2 = rD * X2 + s * (w0 * X1 - w1 * X0) + cm * w2 * wdX + t2;

            float wdD = fmaf(w0, D0, fmaf(w1, D1, w2 * D2));
            float vw0 = rD * D0 + s * (w1 * D2 - w2 * D1) + cm * w0 * wdD;
            float vw1 = rD * D1 + s * (w2 * D0 - w0 * D2) + cm * w1 * wdD;
            float vw2 = rD * D2 + s * (w0 * D1 - w1 * D0) + cm * w2 * wdD;

            out[(size_t)pw * 3 + 0] = xw0;
            out[(size_t)pw * 3 + 1] = xw1;
            out[(size_t)pw * 3 + 2] = xw2;
            size_t off = (size_t)npts * 3;
            out[off + (size_t)pw * 3 + 0] = vw0;
            out[off + (size_t)pw * 3 + 1] = vw1;
            out[off + (size_t)pw * 3 + 2] = vw2;
        }
    }
}

// ---------------------------------------------------------------------------
extern "C" void kernel_launch(void* const* d_in, const int* in_sizes, int n_in,
                              void* d_out, int out_size) {
    const float* xyz    = (const float*)d_in[0];
    const float* vdirs  = (const float*)d_in[1];
    const float* planes = (const float*)d_in[4];
    const float* lines  = (const float*)d_in[5];
    const float* aabb   = (const float*)d_in[6];
    float* out = (float*)d_out;

    const int npts = in_sizes[0] / 3;

    prep_planes<<<dim3(256, 3), 256>>>(planes);
    prep_lines<<<(3 * GRES * LPP + 255) / 256, 256>>>(lines);

    fused_kernel<<<(npts + 7) / 8, 192>>>(xyz, vdirs, aabb, out, npts);
}